// round 5
// baseline (speedup 1.0000x reference)
#include <cuda_runtime.h>
#include <math.h>
#include <stdint.h>

#define BNUM 32
#define LLT 512
#define LST 128
#define CIN 9
#define HDIM 128
#define RNUM 8
#define KWIN 25
#define PADW 12
#define EPSF 1e-5f
#define OUTC 192   // M*3
#define NHTOT 16384  // LST*HDIM
#define NCHUNK 64    // nh chunks of 256

typedef unsigned long long u64;

// -------- scratch (static device, no allocs) --------
__device__ float d_bufA[BNUM*LLT*HDIM];
__device__ float d_bufB[BNUM*LLT*HDIM];
__device__ float d_est [BNUM*LST*HDIM];
__device__ float d_logits[BNUM*RNUM];
__device__ float d_wsel[BNUM];
__device__ int   d_rcount[RNUM];
__device__ int   d_rlist[RNUM*BNUM];
__device__ float d_partial[BNUM*NCHUNK*OUTC];

// -------- f32x2 packed math helpers --------
__device__ __forceinline__ u64 pack2(float lo, float hi){
    u64 d;
    asm("mov.b64 %0, {%1, %2};" : "=l"(d)
        : "r"(__float_as_uint(lo)), "r"(__float_as_uint(hi)));
    return d;
}
__device__ __forceinline__ void unpack2(u64 v, float& lo, float& hi){
    uint32_t a, b;
    asm("mov.b64 {%0, %1}, %2;" : "=r"(a), "=r"(b) : "l"(v));
    lo = __uint_as_float(a); hi = __uint_as_float(b);
}
__device__ __forceinline__ void ffma2(u64& d, u64 a, u64 b, u64 c){
    asm("fma.rn.f32x2 %0, %1, %2, %3;" : "=l"(d) : "l"(a), "l"(b), "l"(c));
}

__device__ __forceinline__ float gelu_exact(float x){
    return 0.5f*x*(1.0f+erff(x*0.7071067811865476f));
}

// reduce 4 values over the NQ threads of each group (NQ = power of 2)
// buf must hold nwarps*4 floats when NQ>32
template<int NQ>
__device__ __forceinline__ void grp_reduce4(float v[4], float* buf, int tid){
    constexpr int SPAN = (NQ < 32) ? NQ : 32;
    #pragma unroll
    for (int i=0;i<4;i++){
        #pragma unroll
        for (int o=SPAN/2; o; o>>=1) v[i] += __shfl_xor_sync(0xffffffffu, v[i], o);
    }
    if (NQ > 32){
        constexpr int NWG = NQ/32;
        int wid = tid>>5, lane = tid&31;
        if (lane==0){
            #pragma unroll
            for (int i=0;i<4;i++) buf[wid*4+i] = v[i];
        }
        __syncthreads();
        int gw0 = (wid/NWG)*NWG;
        #pragma unroll
        for (int i=0;i<4;i++){
            float s = 0.f;
            #pragma unroll
            for (int w=0;w<NWG;w++) s += buf[(gw0+w)*4+i];
            v[i] = s;
        }
        __syncthreads();
    }
}

// ---------------- encode: warp-per-l; x-=x[:,0]; moving avg; two LBR branches ----------------
__global__ void encode_kernel(const float* __restrict__ in,
                              const float* __restrict__ Ws, const float* __restrict__ bs,
                              const float* __restrict__ Wt, const float* __restrict__ bt,
                              float* __restrict__ out, int L){
    int b = blockIdx.y;
    int w = threadIdx.x >> 5, lane = threadIdx.x & 31;
    int l = blockIdx.x*4 + w;
    const float* base = in + (size_t)b*L*CIN;
    float sxl = 0.f, txl = 0.f;
    if (lane < CIN){
        int c = lane;
        float x0 = base[c];
        float xl = base[l*CIN + c];
        float sum = 0.f;
        #pragma unroll
        for (int k=0; k<KWIN; k++){
            int l2 = l - PADW + k;
            l2 = l2 < 0 ? 0 : (l2 > L-1 ? L-1 : l2);
            sum += base[l2*CIN + c];
        }
        float mavg = sum*(1.0f/KWIN);
        sxl = xl - mavg;        // seasonal input
        txl = mavg - x0;        // trend input
    }
    float sx[CIN], tx[CIN];
    #pragma unroll
    for (int c=0;c<CIN;c++){
        sx[c] = __shfl_sync(0xffffffffu, sxl, c);
        tx[c] = __shfl_sync(0xffffffffu, txl, c);
    }
    int h0 = lane*4;
    float4 bsv = *(const float4*)(bs + h0);
    float4 btv = *(const float4*)(bt + h0);
    float s4[4] = {bsv.x, bsv.y, bsv.z, bsv.w};
    float t4[4] = {btv.x, btv.y, btv.z, btv.w};
    #pragma unroll
    for (int c=0;c<CIN;c++){
        float4 wsv = *(const float4*)(Ws + c*HDIM + h0);
        float4 wtv = *(const float4*)(Wt + c*HDIM + h0);
        s4[0]=fmaf(sx[c],wsv.x,s4[0]); s4[1]=fmaf(sx[c],wsv.y,s4[1]);
        s4[2]=fmaf(sx[c],wsv.z,s4[2]); s4[3]=fmaf(sx[c],wsv.w,s4[3]);
        t4[0]=fmaf(tx[c],wtv.x,t4[0]); t4[1]=fmaf(tx[c],wtv.y,t4[1]);
        t4[2]=fmaf(tx[c],wtv.z,t4[2]); t4[3]=fmaf(tx[c],wtv.w,t4[3]);
    }
    float ss = s4[0]+s4[1]+s4[2]+s4[3];
    float ts = t4[0]+t4[1]+t4[2]+t4[3];
    #pragma unroll
    for (int o=16;o;o>>=1){
        ss += __shfl_xor_sync(0xffffffffu, ss, o);
        ts += __shfl_xor_sync(0xffffffffu, ts, o);
    }
    float ms = ss*(1.0f/HDIM), mt = ts*(1.0f/HDIM);
    float ds[4], dt[4];
    float sqs = 0.f, sqt = 0.f;
    #pragma unroll
    for (int i=0;i<4;i++){
        ds[i]=s4[i]-ms; dt[i]=t4[i]-mt;
        sqs = fmaf(ds[i],ds[i],sqs); sqt = fmaf(dt[i],dt[i],sqt);
    }
    #pragma unroll
    for (int o=16;o;o>>=1){
        sqs += __shfl_xor_sync(0xffffffffu, sqs, o);
        sqt += __shfl_xor_sync(0xffffffffu, sqt, o);
    }
    float rs = rsqrtf(sqs*(1.0f/HDIM)+EPSF);
    float rt = rsqrtf(sqt*(1.0f/HDIM)+EPSF);
    float4 y;
    y.x = gelu_exact(ds[0]*rs) + gelu_exact(dt[0]*rt);
    y.y = gelu_exact(ds[1]*rs) + gelu_exact(dt[1]*rt);
    y.z = gelu_exact(ds[2]*rs) + gelu_exact(dt[2]*rt);
    y.w = gelu_exact(ds[3]*rs) + gelu_exact(dt[3]*rt);
    *(float4*)(out + ((size_t)b*L + l)*HDIM + h0) = y;
}

// ---------------- hidden LBR: out[i,h] = gelu(inorm_h(x[i,:]@W[:,h]+b)) ----------------
// j = h quads (NQ=32), G groups of 4 i-rows. blockDim = 128. x dup-packed row-major in smem.
__global__ void hidden_kernel(const float* __restrict__ in, const float* __restrict__ W,
                              const float* __restrict__ bias, float* __restrict__ out, int L){
    constexpr int G = 4, NQ = 32, RPB = 4*G;   // 16 rows/block
    int tid = threadIdx.x;
    int q = tid % NQ, g = tid / NQ;
    int j0 = 4*q;
    int ibase = blockIdx.x * RPB;
    int b = blockIdx.y;
    __shared__ __align__(16) u64 xs[RPB*HDIM];   // [row][k] dup-packed, 16KB
    // fill: coalesced over k
    for (int e = tid; e < RPB*HDIM; e += NQ*G){
        int k = e % HDIM, row = e / HDIM;
        float v = in[((size_t)b*L + ibase + row)*HDIM + k];
        xs[(size_t)row*HDIM + k] = pack2(v, v);
    }
    __syncthreads();
    float4 bv = *(const float4*)(bias + j0);
    u64 acc[4][2];
    #pragma unroll
    for (int r=0;r<4;r++){ acc[r][0] = pack2(bv.x, bv.y); acc[r][1] = pack2(bv.z, bv.w); }
    const u64* xrow = xs + (size_t)(g*4)*HDIM;
    #pragma unroll 8
    for (int k=0;k<HDIM;k++){
        ulonglong2 w2 = *(const ulonglong2*)(W + (size_t)k*HDIM + j0);
        u64 x0 = xrow[k], x1 = xrow[HDIM+k], x2 = xrow[2*HDIM+k], x3 = xrow[3*HDIM+k];
        ffma2(acc[0][0], x0, w2.x, acc[0][0]); ffma2(acc[0][1], x0, w2.y, acc[0][1]);
        ffma2(acc[1][0], x1, w2.x, acc[1][0]); ffma2(acc[1][1], x1, w2.y, acc[1][1]);
        ffma2(acc[2][0], x2, w2.x, acc[2][0]); ffma2(acc[2][1], x2, w2.y, acc[2][1]);
        ffma2(acc[3][0], x3, w2.x, acc[3][0]); ffma2(acc[3][1], x3, w2.y, acc[3][1]);
    }
    float val[4][4];
    #pragma unroll
    for (int r=0;r<4;r++){
        unpack2(acc[r][0], val[r][0], val[r][1]);
        unpack2(acc[r][1], val[r][2], val[r][3]);
    }
    float v[4];
    #pragma unroll
    for (int r=0;r<4;r++) v[r] = val[r][0]+val[r][1]+val[r][2]+val[r][3];
    grp_reduce4<NQ>(v, nullptr, tid);
    float mean[4];
    #pragma unroll
    for (int r=0;r<4;r++) mean[r] = v[r]*(1.0f/HDIM);
    float d[4][4];
    #pragma unroll
    for (int r=0;r<4;r++){
        float sq = 0.f;
        #pragma unroll
        for (int jj=0;jj<4;jj++){ d[r][jj]=val[r][jj]-mean[r]; sq = fmaf(d[r][jj],d[r][jj],sq); }
        v[r] = sq;
    }
    grp_reduce4<NQ>(v, nullptr, tid);
    #pragma unroll
    for (int r=0;r<4;r++){
        float rv = rsqrtf(v[r]*(1.0f/HDIM)+EPSF);
        float4 o4;
        o4.x = gelu_exact(d[r][0]*rv); o4.y = gelu_exact(d[r][1]*rv);
        o4.z = gelu_exact(d[r][2]*rv); o4.w = gelu_exact(d[r][3]*rv);
        *(float4*)(out + ((size_t)b*L + ibase + g*4 + r)*HDIM + j0) = o4;
    }
}

// ---------------- lookback LBR: out[j,h] = gelu(inorm_j(x[h,:]@W[:,j]+b)) ----------------
// j quads (NQ=LOUT/4), G groups of 4 h-rows. blockDim = NQ*G = 128. x dup-packed [l][rows].
template<int LIN, int LOUT, int G>
__global__ void lookback_kernel(const float* __restrict__ in, const float* __restrict__ W,
                                const float* __restrict__ bias, float* __restrict__ out){
    constexpr int NQ = LOUT/4;
    constexpr int NT = NQ*G;
    int tid = threadIdx.x;
    int q = tid % NQ, g = tid / NQ;
    int j0 = 4*q;
    int hbase = blockIdx.x * (4*G);
    int b = blockIdx.y;
    __shared__ __align__(16) u64 xs[LIN*4*G];    // [l][row] dup-packed
    __shared__ float rbuf[(NT/32)*4];
    const float* basein = in + (size_t)b*LIN*HDIM;
    for (int e = tid; e < LIN*2*G; e += NT){
        int pr = e % (2*G);
        int l  = e / (2*G);
        float2 v = *(const float2*)(basein + (size_t)l*HDIM + hbase + 2*pr);
        ulonglong2 dp; dp.x = pack2(v.x, v.x); dp.y = pack2(v.y, v.y);
        *((ulonglong2*)(xs + (size_t)l*(4*G) + 2*pr)) = dp;
    }
    __syncthreads();
    float4 bv = *(const float4*)(bias + j0);
    u64 acc[4][2];
    #pragma unroll
    for (int r=0;r<4;r++){ acc[r][0] = pack2(bv.x, bv.y); acc[r][1] = pack2(bv.z, bv.w); }
    const u64* xbase = xs + g*4;
    #pragma unroll 8
    for (int l=0;l<LIN;l++){
        ulonglong2 w2 = *(const ulonglong2*)(W + (size_t)l*LOUT + j0);
        ulonglong2 xa = *(const ulonglong2*)(xbase + (size_t)l*(4*G));
        ulonglong2 xb = *(const ulonglong2*)(xbase + (size_t)l*(4*G) + 2);
        ffma2(acc[0][0], xa.x, w2.x, acc[0][0]); ffma2(acc[0][1], xa.x, w2.y, acc[0][1]);
        ffma2(acc[1][0], xa.y, w2.x, acc[1][0]); ffma2(acc[1][1], xa.y, w2.y, acc[1][1]);
        ffma2(acc[2][0], xb.x, w2.x, acc[2][0]); ffma2(acc[2][1], xb.x, w2.y, acc[2][1]);
        ffma2(acc[3][0], xb.y, w2.x, acc[3][0]); ffma2(acc[3][1], xb.y, w2.y, acc[3][1]);
    }
    float val[4][4];
    #pragma unroll
    for (int r=0;r<4;r++){
        unpack2(acc[r][0], val[r][0], val[r][1]);
        unpack2(acc[r][1], val[r][2], val[r][3]);
    }
    float v[4];
    #pragma unroll
    for (int r=0;r<4;r++) v[r] = val[r][0]+val[r][1]+val[r][2]+val[r][3];
    grp_reduce4<NQ>(v, rbuf, tid);
    float mean[4];
    #pragma unroll
    for (int r=0;r<4;r++) mean[r] = v[r]*(1.0f/LOUT);
    float d[4][4];
    #pragma unroll
    for (int r=0;r<4;r++){
        float sq = 0.f;
        #pragma unroll
        for (int jj=0;jj<4;jj++){ d[r][jj]=val[r][jj]-mean[r]; sq = fmaf(d[r][jj],d[r][jj],sq); }
        v[r] = sq;
    }
    grp_reduce4<NQ>(v, rbuf, tid);
    float rv[4];
    #pragma unroll
    for (int r=0;r<4;r++) rv[r] = rsqrtf(v[r]*(1.0f/LOUT)+EPSF);
    #pragma unroll
    for (int jj=0;jj<4;jj++){
        float4 o4;
        o4.x = gelu_exact(d[0][jj]*rv[0]);
        o4.y = gelu_exact(d[1][jj]*rv[1]);
        o4.z = gelu_exact(d[2][jj]*rv[2]);
        o4.w = gelu_exact(d[3][jj]*rv[3]);
        *(float4*)(out + ((size_t)b*LOUT + j0 + jj)*HDIM + hbase + g*4) = o4;
    }
}

// ---------------- logits: (B,8192) @ (8192,8) + br ----------------
__global__ void logits_kernel(const float* __restrict__ o, const float* __restrict__ Wr,
                              const float* __restrict__ br, float* __restrict__ logits){
    int b = blockIdx.x, tid = threadIdx.x;  // 256 threads
    float acc[8];
    #pragma unroll
    for (int r=0;r<8;r++) acc[r]=0.f;
    for (int i=tid; i<8192; i+=256){
        float x = o[(size_t)b*8192 + i];
        const float4* w4 = reinterpret_cast<const float4*>(Wr + (size_t)i*8);
        float4 wa = w4[0], wb = w4[1];
        acc[0]=fmaf(x,wa.x,acc[0]); acc[1]=fmaf(x,wa.y,acc[1]);
        acc[2]=fmaf(x,wa.z,acc[2]); acc[3]=fmaf(x,wa.w,acc[3]);
        acc[4]=fmaf(x,wb.x,acc[4]); acc[5]=fmaf(x,wb.y,acc[5]);
        acc[6]=fmaf(x,wb.z,acc[6]); acc[7]=fmaf(x,wb.w,acc[7]);
    }
    __shared__ float sh[8*8];
    #pragma unroll
    for (int r=0;r<8;r++){
        #pragma unroll
        for (int o2=16;o2;o2>>=1) acc[r] += __shfl_xor_sync(0xffffffffu, acc[r], o2);
    }
    int w=tid>>5, lane=tid&31;
    if (lane==0){
        #pragma unroll
        for (int r=0;r<8;r++) sh[r*8+w]=acc[r];
    }
    __syncthreads();
    if (tid<8){
        float s=br[tid];
        #pragma unroll
        for (int ww=0;ww<8;ww++) s+=sh[tid*8+ww];
        logits[b*8+tid]=s;
    }
}

// ---------------- exact JAX threefry2x32 (partitionable) gumbel + hard select + regime lists ----------------
__device__ __forceinline__ uint32_t rotl32(uint32_t x,int r){ return (x<<r)|(x>>(32-r)); }
__device__ __forceinline__ float gumbel_from_bits(uint32_t bits){
    const float tiny = 1.17549435e-38f;
    float f = __uint_as_float((bits>>9)|0x3f800000u) - 1.0f;
    float u = fmaxf(tiny, f + tiny);
    return -logf(-logf(u));
}
__global__ void gumbel_kernel(const float* __restrict__ logits,
                              float* __restrict__ wsel,
                              int* __restrict__ rcount, int* __restrict__ rlist){
    __shared__ float g[256];
    __shared__ int sreg[BNUM];
    int tid = threadIdx.x;  // 256 threads
    {
        uint32_t x0 = 0u, x1 = (uint32_t)tid;
        const uint32_t k0=0u, k1=42u, k2=k0^k1^0x1BD11BDAu;
        x0+=k0; x1+=k1;
        #define TFR(r) { x0+=x1; x1=rotl32(x1,r); x1^=x0; }
        TFR(13)TFR(15)TFR(26)TFR(6)   x0+=k1; x1+=k2+1u;
        TFR(17)TFR(29)TFR(16)TFR(24)  x0+=k2; x1+=k0+2u;
        TFR(13)TFR(15)TFR(26)TFR(6)   x0+=k0; x1+=k1+3u;
        TFR(17)TFR(29)TFR(16)TFR(24)  x0+=k1; x1+=k2+4u;
        TFR(13)TFR(15)TFR(26)TFR(6)   x0+=k2; x1+=k0+5u;
        #undef TFR
        g[tid] = gumbel_from_bits(x0 ^ x1);
    }
    __syncthreads();
    if (tid < BNUM){
        float z[8];
        #pragma unroll
        for (int r=0;r<8;r++) z[r] = logits[tid*8+r] + g[tid*8+r];  // TAU=1
        float mx = z[0]; int am = 0;
        #pragma unroll
        for (int r=1;r<8;r++) if (z[r] > mx){ mx=z[r]; am=r; }
        float sum=0.f;
        #pragma unroll
        for (int r=0;r<8;r++) sum += expf(z[r]-mx);
        float y = 1.0f/sum;
        wsel[tid] = (1.0f - y) + y;
        sreg[tid] = am;
    }
    __syncthreads();
    if (tid == 0){
        int cnt[RNUM];
        #pragma unroll
        for (int r=0;r<RNUM;r++) cnt[r]=0;
        for (int b=0;b<BNUM;b++){
            int r = sreg[b];
            rlist[r*BNUM + cnt[r]] = b;
            cnt[r]++;
        }
        #pragma unroll
        for (int r=0;r<RNUM;r++) rcount[r]=cnt[r];
    }
}

// ---------------- final contraction, regime-grouped, f32x2 over batch pairs ----------------
template<int NP>
__device__ __forceinline__ void fp_body(const u64* __restrict__ es2,
                                        const float* __restrict__ P,
                                        float* __restrict__ partial,
                                        const int* __restrict__ bl,
                                        int nb, int chunk, int t){
    u64 acc[NP];
    #pragma unroll
    for (int q=0;q<NP;q++) acc[q]=0ull;
    #pragma unroll 4
    for (int nh=0; nh<256; nh++){
        float pv = P[(size_t)nh*OUTC];
        u64 pp = pack2(pv, pv);
        const u64* row = es2 + nh*16;
        #pragma unroll
        for (int q=0;q<NP;q++) ffma2(acc[q], row[q], pp, acc[q]);
    }
    #pragma unroll
    for (int q=0;q<NP;q++){
        float lo, hi; unpack2(acc[q], lo, hi);
        partial[((size_t)bl[2*q]*NCHUNK + chunk)*OUTC + t] = lo;
        if (2*q+1 < nb)
            partial[((size_t)bl[2*q+1]*NCHUNK + chunk)*OUTC + t] = hi;
    }
}

__global__ void final_partial(const float* __restrict__ est, const float* __restrict__ proto,
                              const int* __restrict__ rcount, const int* __restrict__ rlist,
                              float* __restrict__ partial){
    int chunk = blockIdx.x, r = blockIdx.y, t = threadIdx.x;  // 192 threads
    int nb = rcount[r];
    if (nb == 0) return;
    int npair = (nb+1)>>1;
    __shared__ __align__(16) u64 es2[256*16];   // [nh][pair] 32KB
    __shared__ int bl[BNUM];
    if (t < BNUM) bl[t] = rlist[r*BNUM + t];
    __syncthreads();
    int nh0 = chunk*256;
    for (int q=0;q<npair;q++){
        int b0 = bl[2*q];
        bool has1 = (2*q+1) < nb;
        const float* e0 = est + (size_t)b0*NHTOT + nh0;
        const float* e1 = has1 ? est + (size_t)bl[2*q+1]*NHTOT + nh0 : e0;
        for (int nh=t; nh<256; nh+=192){
            float lo = e0[nh];
            float hi = has1 ? e1[nh] : 0.f;
            es2[nh*16+q] = pack2(lo, hi);
        }
    }
    __syncthreads();
    const float* P = proto + ((size_t)r*NHTOT + nh0)*OUTC + t;
    switch(npair){
        case 1:  fp_body<1>(es2,P,partial,bl,nb,chunk,t); break;
        case 2:  fp_body<2 >(es2,P,partial,bl,nb,chunk,t); break;
        case 3:  fp_body<3 >(es2,P,partial,bl,nb,chunk,t); break;
        case 4:  fp_body<4 >(es2,P,partial,bl,nb,chunk,t); break;
        case 5:  fp_body<5 >(es2,P,partial,bl,nb,chunk,t); break;
        case 6:  fp_body<6 >(es2,P,partial,bl,nb,chunk,t); break;
        case 7:  fp_body<7 >(es2,P,partial,bl,nb,chunk,t); break;
        case 8:  fp_body<8 >(es2,P,partial,bl,nb,chunk,t); break;
        case 9:  fp_body<9 >(es2,P,partial,bl,nb,chunk,t); break;
        case 10: fp_body<10>(es2,P,partial,bl,nb,chunk,t); break;
        case 11: fp_body<11>(es2,P,partial,bl,nb,chunk,t); break;
        case 12: fp_body<12>(es2,P,partial,bl,nb,chunk,t); break;
        case 13: fp_body<13>(es2,P,partial,bl,nb,chunk,t); break;
        case 14: fp_body<14>(es2,P,partial,bl,nb,chunk,t); break;
        case 15: fp_body<15>(es2,P,partial,bl,nb,chunk,t); break;
        default: fp_body<16>(es2,P,partial,bl,nb,chunk,t); break;
    }
}

__global__ void final_softmax(const float* __restrict__ partial, const float* __restrict__ wsel,
                              float* __restrict__ out){
    int b = blockIdx.x, t = threadIdx.x;  // 192 threads = 6 warps
    float s = 0.f;
    #pragma unroll 8
    for (int ch=0; ch<NCHUNK; ch++) s += partial[((size_t)b*NCHUNK+ch)*OUTC + t];
    s *= wsel[b];
    __shared__ float shm[6], shs[6];
    float m = s;
    #pragma unroll
    for (int o=16;o;o>>=1) m = fmaxf(m, __shfl_xor_sync(0xffffffffu, m, o));
    if ((t&31)==0) shm[t>>5]=m;
    __syncthreads();
    m = shm[0];
    #pragma unroll
    for (int w=1;w<6;w++) m = fmaxf(m, shm[w]);
    float e = expf(s-m);
    float su = e;
    #pragma unroll
    for (int o=16;o;o>>=1) su += __shfl_xor_sync(0xffffffffu, su, o);
    if ((t&31)==0) shs[t>>5]=su;
    __syncthreads();
    su = 0.f;
    #pragma unroll
    for (int w=0;w<6;w++) su += shs[w];
    out[(size_t)b*OUTC + t] = e/su;
}

// ---------------- launch ----------------
extern "C" void kernel_launch(void* const* d_in, const int* in_sizes, int n_in,
                              void* d_out, int out_size){
    (void)in_sizes; (void)n_in; (void)out_size;
    const float* in_lt = (const float*)d_in[0];
    const float* in_st = (const float*)d_in[1];
    const float* Ws  = (const float*)d_in[2];  const float* bs  = (const float*)d_in[3];
    const float* Wt  = (const float*)d_in[4];  const float* bt  = (const float*)d_in[5];
    const float* Wh1 = (const float*)d_in[6];  const float* bh1 = (const float*)d_in[7];
    const float* Wl1 = (const float*)d_in[8];  const float* bl1 = (const float*)d_in[9];
    const float* Wh2 = (const float*)d_in[10]; const float* bh2 = (const float*)d_in[11];
    const float* Wl2 = (const float*)d_in[12]; const float* bl2 = (const float*)d_in[13];
    const float* Wh3 = (const float*)d_in[14]; const float* bh3 = (const float*)d_in[15];
    const float* Wl3 = (const float*)d_in[16]; const float* bl3 = (const float*)d_in[17];
    const float* Wr  = (const float*)d_in[18]; const float* br  = (const float*)d_in[19];
    const float* proto = (const float*)d_in[20];

    float *bufA, *bufB, *est, *logits, *wsel, *partial; int *rcount, *rlist;
    cudaGetSymbolAddress((void**)&bufA,    d_bufA);
    cudaGetSymbolAddress((void**)&bufB,    d_bufB);
    cudaGetSymbolAddress((void**)&est,     d_est);
    cudaGetSymbolAddress((void**)&logits,  d_logits);
    cudaGetSymbolAddress((void**)&wsel,    d_wsel);
    cudaGetSymbolAddress((void**)&rcount,  d_rcount);
    cudaGetSymbolAddress((void**)&rlist,   d_rlist);
    cudaGetSymbolAddress((void**)&partial, d_partial);

    encode_kernel<<<dim3(LLT/4,BNUM), 128>>>(in_lt, Ws, bs, Wt, bt, bufA, LLT);
    encode_kernel<<<dim3(LST/4,BNUM), 128>>>(in_st, Ws, bs, Wt, bt, est,  LST);

    hidden_kernel<<<dim3(LLT/16,BNUM), 128>>>(bufA, Wh1, bh1, bufB, LLT);
    lookback_kernel<512,256,2><<<dim3(16,BNUM), 128>>>(bufB, Wl1, bl1, bufA);
    hidden_kernel<<<dim3(256/16,BNUM), 128>>>(bufA, Wh2, bh2, bufB, 256);
    lookback_kernel<256,128,4><<<dim3(8,BNUM), 128>>>(bufB, Wl2, bl2, bufA);
    hidden_kernel<<<dim3(128/16,BNUM), 128>>>(bufA, Wh3, bh3, bufB, 128);
    lookback_kernel<128,64,8><<<dim3(4,BNUM), 128>>>(bufB, Wl3, bl3, bufA);

    logits_kernel<<<BNUM, 256>>>(bufA, Wr, br, logits);
    gumbel_kernel<<<1, 256>>>(logits, wsel, rcount, rlist);

    final_partial<<<dim3(NCHUNK,RNUM), OUTC>>>(est, proto, rcount, rlist, partial);
    final_softmax<<<BNUM, OUTC>>>(partial, wsel, (float*)d_out);
}

// round 6
// speedup vs baseline: 1.3021x; 1.3021x over previous
#include <cuda_runtime.h>
#include <math.h>
#include <stdint.h>

#define BNUM 32
#define LLT 512
#define LST 128
#define CIN 9
#define HDIM 128
#define RNUM 8
#define KWIN 25
#define PADW 12
#define EPSF 1e-5f
#define OUTC 192   // M*3
#define NHTOT 16384  // LST*HDIM
#define NCHUNK 64    // nh chunks of 256

typedef unsigned long long u64;

// -------- scratch (static device, no allocs) --------
__device__ float d_bufA[BNUM*LLT*HDIM];
__device__ float d_bufB[BNUM*LLT*HDIM];
__device__ float d_est [BNUM*LST*HDIM];
__device__ float d_logits[BNUM*RNUM];
__device__ float d_wsel[BNUM];
__device__ int   d_rcount[RNUM];
__device__ int   d_rlist[RNUM*BNUM];
__device__ float d_partial[BNUM*NCHUNK*OUTC];

// -------- f32x2 packed math helpers --------
__device__ __forceinline__ u64 pack2(float lo, float hi){
    u64 d;
    asm("mov.b64 %0, {%1, %2};" : "=l"(d)
        : "r"(__float_as_uint(lo)), "r"(__float_as_uint(hi)));
    return d;
}
__device__ __forceinline__ void unpack2(u64 v, float& lo, float& hi){
    uint32_t a, b;
    asm("mov.b64 {%0, %1}, %2;" : "=r"(a), "=r"(b) : "l"(v));
    lo = __uint_as_float(a); hi = __uint_as_float(b);
}
__device__ __forceinline__ void ffma2(u64& d, u64 a, u64 b, u64 c){
    asm("fma.rn.f32x2 %0, %1, %2, %3;" : "=l"(d) : "l"(a), "l"(b), "l"(c));
}

__device__ __forceinline__ float gelu_exact(float x){
    return 0.5f*x*(1.0f+erff(x*0.7071067811865476f));
}

// reduce 4 values over the NQ threads of each tid-contiguous group (NQ = 32/64/128)
// buf must hold (blockDim/32)*4 floats when NQ>32
template<int NQ>
__device__ __forceinline__ void grp_reduce4(float v[4], float* buf, int tid){
    #pragma unroll
    for (int i=0;i<4;i++){
        #pragma unroll
        for (int o=16; o; o>>=1) v[i] += __shfl_xor_sync(0xffffffffu, v[i], o);
    }
    if (NQ > 32){
        constexpr int NWG = NQ/32;
        int wid = tid>>5, lane = tid&31;
        if (lane==0){
            #pragma unroll
            for (int i=0;i<4;i++) buf[wid*4+i] = v[i];
        }
        __syncthreads();
        int gw0 = (wid/NWG)*NWG;
        #pragma unroll
        for (int i=0;i<4;i++){
            float s = 0.f;
            #pragma unroll
            for (int w=0;w<NWG;w++) s += buf[(gw0+w)*4+i];
            v[i] = s;
        }
        __syncthreads();
    }
}

// ---------------- encode: warp-per-l; x-=x[:,0]; moving avg; two LBR branches ----------------
__global__ void encode_kernel(const float* __restrict__ in,
                              const float* __restrict__ Ws, const float* __restrict__ bs,
                              const float* __restrict__ Wt, const float* __restrict__ bt,
                              float* __restrict__ out, int L){
    int b = blockIdx.y;
    int w = threadIdx.x >> 5, lane = threadIdx.x & 31;
    int l = blockIdx.x*4 + w;
    const float* base = in + (size_t)b*L*CIN;
    float sxl = 0.f, txl = 0.f;
    if (lane < CIN){
        int c = lane;
        float x0 = base[c];
        float xl = base[l*CIN + c];
        float sum = 0.f;
        #pragma unroll
        for (int k=0; k<KWIN; k++){
            int l2 = l - PADW + k;
            l2 = l2 < 0 ? 0 : (l2 > L-1 ? L-1 : l2);
            sum += base[l2*CIN + c];
        }
        float mavg = sum*(1.0f/KWIN);
        sxl = xl - mavg;        // seasonal input
        txl = mavg - x0;        // trend input
    }
    float sx[CIN], tx[CIN];
    #pragma unroll
    for (int c=0;c<CIN;c++){
        sx[c] = __shfl_sync(0xffffffffu, sxl, c);
        tx[c] = __shfl_sync(0xffffffffu, txl, c);
    }
    int h0 = lane*4;
    float4 bsv = *(const float4*)(bs + h0);
    float4 btv = *(const float4*)(bt + h0);
    float s4[4] = {bsv.x, bsv.y, bsv.z, bsv.w};
    float t4[4] = {btv.x, btv.y, btv.z, btv.w};
    #pragma unroll
    for (int c=0;c<CIN;c++){
        float4 wsv = *(const float4*)(Ws + c*HDIM + h0);
        float4 wtv = *(const float4*)(Wt + c*HDIM + h0);
        s4[0]=fmaf(sx[c],wsv.x,s4[0]); s4[1]=fmaf(sx[c],wsv.y,s4[1]);
        s4[2]=fmaf(sx[c],wsv.z,s4[2]); s4[3]=fmaf(sx[c],wsv.w,s4[3]);
        t4[0]=fmaf(tx[c],wtv.x,t4[0]); t4[1]=fmaf(tx[c],wtv.y,t4[1]);
        t4[2]=fmaf(tx[c],wtv.z,t4[2]); t4[3]=fmaf(tx[c],wtv.w,t4[3]);
    }
    float ss = s4[0]+s4[1]+s4[2]+s4[3];
    float ts = t4[0]+t4[1]+t4[2]+t4[3];
    #pragma unroll
    for (int o=16;o;o>>=1){
        ss += __shfl_xor_sync(0xffffffffu, ss, o);
        ts += __shfl_xor_sync(0xffffffffu, ts, o);
    }
    float ms = ss*(1.0f/HDIM), mt = ts*(1.0f/HDIM);
    float ds[4], dt[4];
    float sqs = 0.f, sqt = 0.f;
    #pragma unroll
    for (int i=0;i<4;i++){
        ds[i]=s4[i]-ms; dt[i]=t4[i]-mt;
        sqs = fmaf(ds[i],ds[i],sqs); sqt = fmaf(dt[i],dt[i],sqt);
    }
    #pragma unroll
    for (int o=16;o;o>>=1){
        sqs += __shfl_xor_sync(0xffffffffu, sqs, o);
        sqt += __shfl_xor_sync(0xffffffffu, sqt, o);
    }
    float rs = rsqrtf(sqs*(1.0f/HDIM)+EPSF);
    float rt = rsqrtf(sqt*(1.0f/HDIM)+EPSF);
    float4 y;
    y.x = gelu_exact(ds[0]*rs) + gelu_exact(dt[0]*rt);
    y.y = gelu_exact(ds[1]*rs) + gelu_exact(dt[1]*rt);
    y.z = gelu_exact(ds[2]*rs) + gelu_exact(dt[2]*rt);
    y.w = gelu_exact(ds[3]*rs) + gelu_exact(dt[3]*rt);
    *(float4*)(out + ((size_t)b*L + l)*HDIM + h0) = y;
}

// ---------------- hidden LBR: out[i,j] = gelu(inorm_j(x[i,:]@W[:,j]+b)) ----------------
// 2j x 4i register tile. NJP=64 j-pairs, G=2 i-groups of 4 -> 128 threads, 8 rows/block.
// Per k: LDG.64 (W j-pair) + LDS.128 (4 i natural pairs, broadcast) + 2 dup movs + 4 FFMA2.
__global__ void hidden_kernel(const float* __restrict__ in, const float* __restrict__ W,
                              const float* __restrict__ bias, float* __restrict__ out, int L){
    constexpr int NJP = 64, G = 2, NT = NJP*G, RPB = 4*G;  // 8 rows/block
    int tid = threadIdx.x;
    int q = tid % NJP, g = tid / NJP;
    int j0 = 2*q;
    int ibase = blockIdx.x * RPB;
    int b = blockIdx.y;
    __shared__ __align__(16) float xs[HDIM*RPB];   // [k][row] natural, 4KB
    __shared__ float rbuf[(NT/32)*4];
    const float* basein = in + ((size_t)b*L + ibase)*HDIM;
    // transposing fill (coalesced gmem reads)
    for (int e = tid; e < RPB*HDIM; e += NT){
        int row = e / HDIM, k = e % HDIM;
        xs[k*RPB + row] = basein[(size_t)row*HDIM + k];
    }
    __syncthreads();
    float2 bv = *(const float2*)(bias + j0);
    u64 acc[2][2];   // [ipair][j]
    acc[0][0] = pack2(bv.x, bv.x); acc[1][0] = acc[0][0];
    acc[0][1] = pack2(bv.y, bv.y); acc[1][1] = acc[0][1];
    #pragma unroll 8
    for (int k=0;k<HDIM;k++){
        float2 w2 = *(const float2*)(W + (size_t)k*HDIM + j0);
        ulonglong2 xa = *(const ulonglong2*)(xs + k*RPB + g*4);  // rows g*4..g*4+3
        u64 w0d = pack2(w2.x, w2.x);
        u64 w1d = pack2(w2.y, w2.y);
        ffma2(acc[0][0], xa.x, w0d, acc[0][0]);
        ffma2(acc[1][0], xa.y, w0d, acc[1][0]);
        ffma2(acc[0][1], xa.x, w1d, acc[0][1]);
        ffma2(acc[1][1], xa.y, w1d, acc[1][1]);
    }
    float val[4][2];   // [i local][j]
    unpack2(acc[0][0], val[0][0], val[1][0]);
    unpack2(acc[1][0], val[2][0], val[3][0]);
    unpack2(acc[0][1], val[0][1], val[1][1]);
    unpack2(acc[1][1], val[2][1], val[3][1]);
    float v[4];
    #pragma unroll
    for (int i=0;i<4;i++) v[i] = val[i][0] + val[i][1];
    grp_reduce4<NJP>(v, rbuf, tid);
    float mean[4];
    #pragma unroll
    for (int i=0;i<4;i++) mean[i] = v[i]*(1.0f/HDIM);
    float d[4][2];
    #pragma unroll
    for (int i=0;i<4;i++){
        d[i][0] = val[i][0]-mean[i];
        d[i][1] = val[i][1]-mean[i];
        v[i] = fmaf(d[i][0],d[i][0], d[i][1]*d[i][1]);
    }
    grp_reduce4<NJP>(v, rbuf, tid);
    #pragma unroll
    for (int i=0;i<4;i++){
        float rv = rsqrtf(v[i]*(1.0f/HDIM)+EPSF);
        float2 o2;
        o2.x = gelu_exact(d[i][0]*rv);
        o2.y = gelu_exact(d[i][1]*rv);
        *(float2*)(out + ((size_t)b*L + ibase + g*4 + i)*HDIM + j0) = o2;
    }
}

// ---------------- lookback LBR: out[j,h] = gelu(inorm_j(x[h,:]@W[:,j]+b)) ----------------
// 2j x 4h register tile. NJP=LOUT/2 j-pairs, G h-groups of 4, blockDim = NJP*G.
// Per l: LDG.64 (W j-pair) + LDS.128 (4 h natural pairs, broadcast) + 2 dup movs + 4 FFMA2.
template<int LIN, int LOUT, int G>
__global__ void lookback_kernel(const float* __restrict__ in, const float* __restrict__ W,
                                const float* __restrict__ bias, float* __restrict__ out){
    constexpr int NJP = LOUT/2;
    constexpr int NT = NJP*G;
    int tid = threadIdx.x;
    int q = tid % NJP, g = tid / NJP;
    int j0 = 2*q;
    int hbase_blk = blockIdx.x * (4*G);
    int b = blockIdx.y;
    __shared__ __align__(16) float xs[LIN*4*G];   // [l][h-local] natural floats
    __shared__ float rbuf[(NT/32)*4];
    const float* basein = in + (size_t)b*LIN*HDIM + hbase_blk;
    // vectorized fill: LIN*G float4s
    for (int e = tid; e < LIN*G; e += NT){
        int l = e / G, f4 = e % G;
        float4 vv = *(const float4*)(basein + (size_t)l*HDIM + f4*4);
        *(float4*)(xs + l*(4*G) + f4*4) = vv;
    }
    __syncthreads();
    float2 bv = *(const float2*)(bias + j0);
    u64 acc[2][2];   // [hpair][j]
    acc[0][0] = pack2(bv.x, bv.x); acc[1][0] = acc[0][0];
    acc[0][1] = pack2(bv.y, bv.y); acc[1][1] = acc[0][1];
    #pragma unroll 8
    for (int l=0;l<LIN;l++){
        float2 w2 = *(const float2*)(W + (size_t)l*LOUT + j0);
        ulonglong2 xa = *(const ulonglong2*)(xs + l*(4*G) + g*4);  // h g*4..g*4+3
        u64 w0d = pack2(w2.x, w2.x);
        u64 w1d = pack2(w2.y, w2.y);
        ffma2(acc[0][0], xa.x, w0d, acc[0][0]);
        ffma2(acc[1][0], xa.y, w0d, acc[1][0]);
        ffma2(acc[0][1], xa.x, w1d, acc[0][1]);
        ffma2(acc[1][1], xa.y, w1d, acc[1][1]);
    }
    float val[4][2];   // [h local][j]
    unpack2(acc[0][0], val[0][0], val[1][0]);
    unpack2(acc[1][0], val[2][0], val[3][0]);
    unpack2(acc[0][1], val[0][1], val[1][1]);
    unpack2(acc[1][1], val[2][1], val[3][1]);
    float v[4];
    #pragma unroll
    for (int h=0;h<4;h++) v[h] = val[h][0] + val[h][1];
    grp_reduce4<NJP>(v, rbuf, tid);
    float mean[4];
    #pragma unroll
    for (int h=0;h<4;h++) mean[h] = v[h]*(1.0f/LOUT);
    float d[4][2];
    #pragma unroll
    for (int h=0;h<4;h++){
        d[h][0] = val[h][0]-mean[h];
        d[h][1] = val[h][1]-mean[h];
        v[h] = fmaf(d[h][0],d[h][0], d[h][1]*d[h][1]);
    }
    grp_reduce4<NJP>(v, rbuf, tid);
    float rv[4];
    #pragma unroll
    for (int h=0;h<4;h++) rv[h] = rsqrtf(v[h]*(1.0f/LOUT)+EPSF);
    #pragma unroll
    for (int j=0;j<2;j++){
        float4 o4;
        o4.x = gelu_exact(d[0][j]*rv[0]);
        o4.y = gelu_exact(d[1][j]*rv[1]);
        o4.z = gelu_exact(d[2][j]*rv[2]);
        o4.w = gelu_exact(d[3][j]*rv[3]);
        *(float4*)(out + ((size_t)b*LOUT + j0 + j)*HDIM + hbase_blk + g*4) = o4;
    }
}

// ---------------- logits: (B,8192) @ (8192,8) + br ----------------
__global__ void logits_kernel(const float* __restrict__ o, const float* __restrict__ Wr,
                              const float* __restrict__ br, float* __restrict__ logits){
    int b = blockIdx.x, tid = threadIdx.x;  // 256 threads
    float acc[8];
    #pragma unroll
    for (int r=0;r<8;r++) acc[r]=0.f;
    for (int i=tid; i<8192; i+=256){
        float x = o[(size_t)b*8192 + i];
        const float4* w4 = reinterpret_cast<const float4*>(Wr + (size_t)i*8);
        float4 wa = w4[0], wb = w4[1];
        acc[0]=fmaf(x,wa.x,acc[0]); acc[1]=fmaf(x,wa.y,acc[1]);
        acc[2]=fmaf(x,wa.z,acc[2]); acc[3]=fmaf(x,wa.w,acc[3]);
        acc[4]=fmaf(x,wb.x,acc[4]); acc[5]=fmaf(x,wb.y,acc[5]);
        acc[6]=fmaf(x,wb.z,acc[6]); acc[7]=fmaf(x,wb.w,acc[7]);
    }
    __shared__ float sh[8*8];
    #pragma unroll
    for (int r=0;r<8;r++){
        #pragma unroll
        for (int o2=16;o2;o2>>=1) acc[r] += __shfl_xor_sync(0xffffffffu, acc[r], o2);
    }
    int w=tid>>5, lane=tid&31;
    if (lane==0){
        #pragma unroll
        for (int r=0;r<8;r++) sh[r*8+w]=acc[r];
    }
    __syncthreads();
    if (tid<8){
        float s=br[tid];
        #pragma unroll
        for (int ww=0;ww<8;ww++) s+=sh[tid*8+ww];
        logits[b*8+tid]=s;
    }
}

// ---------------- exact JAX threefry2x32 (partitionable) gumbel + hard select + regime lists ----------------
__device__ __forceinline__ uint32_t rotl32(uint32_t x,int r){ return (x<<r)|(x>>(32-r)); }
__device__ __forceinline__ float gumbel_from_bits(uint32_t bits){
    const float tiny = 1.17549435e-38f;
    float f = __uint_as_float((bits>>9)|0x3f800000u) - 1.0f;
    float u = fmaxf(tiny, f + tiny);
    return -logf(-logf(u));
}
__global__ void gumbel_kernel(const float* __restrict__ logits,
                              float* __restrict__ wsel,
                              int* __restrict__ rcount, int* __restrict__ rlist){
    __shared__ float g[256];
    __shared__ int sreg[BNUM];
    int tid = threadIdx.x;  // 256 threads
    {
        uint32_t x0 = 0u, x1 = (uint32_t)tid;
        const uint32_t k0=0u, k1=42u, k2=k0^k1^0x1BD11BDAu;
        x0+=k0; x1+=k1;
        #define TFR(r) { x0+=x1; x1=rotl32(x1,r); x1^=x0; }
        TFR(13)TFR(15)TFR(26)TFR(6)   x0+=k1; x1+=k2+1u;
        TFR(17)TFR(29)TFR(16)TFR(24)  x0+=k2; x1+=k0+2u;
        TFR(13)TFR(15)TFR(26)TFR(6)   x0+=k0; x1+=k1+3u;
        TFR(17)TFR(29)TFR(16)TFR(24)  x0+=k1; x1+=k2+4u;
        TFR(13)TFR(15)TFR(26)TFR(6)   x0+=k2; x1+=k0+5u;
        #undef TFR
        g[tid] = gumbel_from_bits(x0 ^ x1);
    }
    __syncthreads();
    if (tid < BNUM){
        float z[8];
        #pragma unroll
        for (int r=0;r<8;r++) z[r] = logits[tid*8+r] + g[tid*8+r];  // TAU=1
        float mx = z[0]; int am = 0;
        #pragma unroll
        for (int r=1;r<8;r++) if (z[r] > mx){ mx=z[r]; am=r; }
        float sum=0.f;
        #pragma unroll
        for (int r=0;r<8;r++) sum += expf(z[r]-mx);
        float y = 1.0f/sum;
        wsel[tid] = (1.0f - y) + y;
        sreg[tid] = am;
    }
    __syncthreads();
    if (tid == 0){
        int cnt[RNUM];
        #pragma unroll
        for (int r=0;r<RNUM;r++) cnt[r]=0;
        for (int b=0;b<BNUM;b++){
            int r = sreg[b];
            rlist[r*BNUM + cnt[r]] = b;
            cnt[r]++;
        }
        #pragma unroll
        for (int r=0;r<RNUM;r++) rcount[r]=cnt[r];
    }
}

// ---------------- final contraction, regime-grouped, f32x2 over batch pairs ----------------
template<int NP>
__device__ __forceinline__ void fp_body(const u64* __restrict__ es2,
                                        const float* __restrict__ P,
                                        float* __restrict__ partial,
                                        const int* __restrict__ bl,
                                        int nb, int chunk, int t){
    u64 acc[NP];
    #pragma unroll
    for (int q=0;q<NP;q++) acc[q]=0ull;
    #pragma unroll 4
    for (int nh=0; nh<256; nh++){
        float pv = P[(size_t)nh*OUTC];
        u64 pp = pack2(pv, pv);
        const u64* row = es2 + nh*16;
        #pragma unroll
        for (int q=0;q<NP;q++) ffma2(acc[q], row[q], pp, acc[q]);
    }
    #pragma unroll
    for (int q=0;q<NP;q++){
        float lo, hi; unpack2(acc[q], lo, hi);
        partial[((size_t)bl[2*q]*NCHUNK + chunk)*OUTC + t] = lo;
        if (2*q+1 < nb)
            partial[((size_t)bl[2*q+1]*NCHUNK + chunk)*OUTC + t] = hi;
    }
}

__global__ void final_partial(const float* __restrict__ est, const float* __restrict__ proto,
                              const int* __restrict__ rcount, const int* __restrict__ rlist,
                              float* __restrict__ partial){
    int chunk = blockIdx.x, r = blockIdx.y, t = threadIdx.x;  // 192 threads
    int nb = rcount[r];
    if (nb == 0) return;
    int npair = (nb+1)>>1;
    __shared__ __align__(16) u64 es2[256*16];   // [nh][pair] 32KB
    __shared__ int bl[BNUM];
    if (t < BNUM) bl[t] = rlist[r*BNUM + t];
    __syncthreads();
    int nh0 = chunk*256;
    for (int q=0;q<npair;q++){
        int b0 = bl[2*q];
        bool has1 = (2*q+1) < nb;
        const float* e0 = est + (size_t)b0*NHTOT + nh0;
        const float* e1 = has1 ? est + (size_t)bl[2*q+1]*NHTOT + nh0 : e0;
        for (int nh=t; nh<256; nh+=192){
            float lo = e0[nh];
            float hi = has1 ? e1[nh] : 0.f;
            es2[nh*16+q] = pack2(lo, hi);
        }
    }
    __syncthreads();
    const float* P = proto + ((size_t)r*NHTOT + nh0)*OUTC + t;
    switch(npair){
        case 1:  fp_body<1>(es2,P,partial,bl,nb,chunk,t); break;
        case 2:  fp_body<2 >(es2,P,partial,bl,nb,chunk,t); break;
        case 3:  fp_body<3 >(es2,P,partial,bl,nb,chunk,t); break;
        case 4:  fp_body<4 >(es2,P,partial,bl,nb,chunk,t); break;
        case 5:  fp_body<5 >(es2,P,partial,bl,nb,chunk,t); break;
        case 6:  fp_body<6 >(es2,P,partial,bl,nb,chunk,t); break;
        case 7:  fp_body<7 >(es2,P,partial,bl,nb,chunk,t); break;
        case 8:  fp_body<8 >(es2,P,partial,bl,nb,chunk,t); break;
        case 9:  fp_body<9 >(es2,P,partial,bl,nb,chunk,t); break;
        case 10: fp_body<10>(es2,P,partial,bl,nb,chunk,t); break;
        case 11: fp_body<11>(es2,P,partial,bl,nb,chunk,t); break;
        case 12: fp_body<12>(es2,P,partial,bl,nb,chunk,t); break;
        case 13: fp_body<13>(es2,P,partial,bl,nb,chunk,t); break;
        case 14: fp_body<14>(es2,P,partial,bl,nb,chunk,t); break;
        case 15: fp_body<15>(es2,P,partial,bl,nb,chunk,t); break;
        default: fp_body<16>(es2,P,partial,bl,nb,chunk,t); break;
    }
}

__global__ void final_softmax(const float* __restrict__ partial, const float* __restrict__ wsel,
                              float* __restrict__ out){
    int b = blockIdx.x, t = threadIdx.x;  // 192 threads = 6 warps
    float s = 0.f;
    #pragma unroll 8
    for (int ch=0; ch<NCHUNK; ch++) s += partial[((size_t)b*NCHUNK+ch)*OUTC + t];
    s *= wsel[b];
    __shared__ float shm[6], shs[6];
    float m = s;
    #pragma unroll
    for (int o=16;o;o>>=1) m = fmaxf(m, __shfl_xor_sync(0xffffffffu, m, o));
    if ((t&31)==0) shm[t>>5]=m;
    __syncthreads();
    m = shm[0];
    #pragma unroll
    for (int w=1;w<6;w++) m = fmaxf(m, shm[w]);
    float e = expf(s-m);
    float su = e;
    #pragma unroll
    for (int o=16;o;o>>=1) su += __shfl_xor_sync(0xffffffffu, su, o);
    if ((t&31)==0) shs[t>>5]=su;
    __syncthreads();
    su = 0.f;
    #pragma unroll
    for (int w=0;w<6;w++) su += shs[w];
    out[(size_t)b*OUTC + t] = e/su;
}

// ---------------- launch ----------------
extern "C" void kernel_launch(void* const* d_in, const int* in_sizes, int n_in,
                              void* d_out, int out_size){
    (void)in_sizes; (void)n_in; (void)out_size;
    const float* in_lt = (const float*)d_in[0];
    const float* in_st = (const float*)d_in[1];
    const float* Ws  = (const float*)d_in[2];  const float* bs  = (const float*)d_in[3];
    const float* Wt  = (const float*)d_in[4];  const float* bt  = (const float*)d_in[5];
    const float* Wh1 = (const float*)d_in[6];  const float* bh1 = (const float*)d_in[7];
    const float* Wl1 = (const float*)d_in[8];  const float* bl1 = (const float*)d_in[9];
    const float* Wh2 = (const float*)d_in[10]; const float* bh2 = (const float*)d_in[11];
    const float* Wl2 = (const float*)d_in[12]; const float* bl2 = (const float*)d_in[13];
    const float* Wh3 = (const float*)d_in[14]; const float* bh3 = (const float*)d_in[15];
    const float* Wl3 = (const float*)d_in[16]; const float* bl3 = (const float*)d_in[17];
    const float* Wr  = (const float*)d_in[18]; const float* br  = (const float*)d_in[19];
    const float* proto = (const float*)d_in[20];

    float *bufA, *bufB, *est, *logits, *wsel, *partial; int *rcount, *rlist;
    cudaGetSymbolAddress((void**)&bufA,    d_bufA);
    cudaGetSymbolAddress((void**)&bufB,    d_bufB);
    cudaGetSymbolAddress((void**)&est,     d_est);
    cudaGetSymbolAddress((void**)&logits,  d_logits);
    cudaGetSymbolAddress((void**)&wsel,    d_wsel);
    cudaGetSymbolAddress((void**)&rcount,  d_rcount);
    cudaGetSymbolAddress((void**)&rlist,   d_rlist);
    cudaGetSymbolAddress((void**)&partial, d_partial);

    encode_kernel<<<dim3(LLT/4,BNUM), 128>>>(in_lt, Ws, bs, Wt, bt, bufA, LLT);
    encode_kernel<<<dim3(LST/4,BNUM), 128>>>(in_st, Ws, bs, Wt, bt, est,  LST);

    // hidden: 8 rows/block, 128 threads
    hidden_kernel<<<dim3(LLT/8,BNUM), 128>>>(bufA, Wh1, bh1, bufB, LLT);
    // lookback1: LOUT=256 -> NJP=128, G=2 -> 256 thr, grid (128/(4*2)=16, B)
    lookback_kernel<512,256,2><<<dim3(16,BNUM), 256>>>(bufB, Wl1, bl1, bufA);
    hidden_kernel<<<dim3(256/8,BNUM), 128>>>(bufA, Wh2, bh2, bufB, 256);
    // lookback2: LOUT=128 -> NJP=64, G=4 -> 256 thr, grid (128/16=8, B)
    lookback_kernel<256,128,4><<<dim3(8,BNUM), 256>>>(bufB, Wl2, bl2, bufA);
    hidden_kernel<<<dim3(128/8,BNUM), 128>>>(bufA, Wh3, bh3, bufB, 128);
    // lookback3: LOUT=64 -> NJP=32, G=8 -> 256 thr, grid (128/32=4, B)
    lookback_kernel<128,64,8><<<dim3(4,BNUM), 256>>>(bufB, Wl3, bl3, bufA);

    logits_kernel<<<BNUM, 256>>>(bufA, Wr, br, logits);
    gumbel_kernel<<<1, 256>>>(logits, wsel, rcount, rlist);

    final_partial<<<dim3(NCHUNK,RNUM), OUTC>>>(est, proto, rcount, rlist, partial);
    final_softmax<<<BNUM, OUTC>>>(partial, wsel, (float*)d_out);
}